// round 9
// baseline (speedup 1.0000x reference)
#include <cuda_runtime.h>
#include <stdint.h>

#define N_NODES 50000
#define N_EDGES 800000
#define D 64
#define N_LAYERS 12

typedef unsigned long long u64;

__device__ float g_aggr[N_NODES * D];
__device__ float g_buf0[N_NODES * D];
__device__ float g_buf1[N_NODES * D];
// CSR-sorted edge arrays (built once per launch)
__device__ int   g_deg[N_NODES];
__device__ int   g_cur[N_NODES];
__device__ int   g_src[N_EDGES];
__device__ int   g_dst[N_EDGES];
__device__ float g_w[N_EDGES];

// ---------------------------------------------------------------------------
// CSR build: histogram -> scan -> permute (sort edges by dst)
// ---------------------------------------------------------------------------
__global__ void hist_kernel(const int* __restrict__ ei) {
    int e = blockIdx.x * blockDim.x + threadIdx.x;
    if (e < N_EDGES) atomicAdd(&g_deg[ei[N_EDGES + e]], 1);
}

#define SCAN_T 1024
#define SCAN_C 49
__global__ void scan_kernel() {
    __shared__ int part[SCAN_T];
    int t = threadIdx.x;
    int base = t * SCAN_C;
    int s = 0;
    for (int j = 0; j < SCAN_C; ++j) {   // let compiler unroll & batch loads
        int idx = base + j;
        if (idx < N_NODES) s += g_deg[idx];
    }
    part[t] = s;
    __syncthreads();
    for (int off = 1; off < SCAN_T; off <<= 1) {
        int v = (t >= off) ? part[t - off] : 0;
        __syncthreads();
        part[t] += v;
        __syncthreads();
    }
    int run = (t > 0) ? part[t - 1] : 0;
    for (int j = 0; j < SCAN_C; ++j) {
        int idx = base + j;
        if (idx < N_NODES) {
            g_cur[idx] = run;
            run += g_deg[idx];
        }
    }
}

__global__ void permute_kernel(const int* __restrict__ ei,
                               const float* __restrict__ ew) {
    int e = blockIdx.x * blockDim.x + threadIdx.x;
    if (e >= N_EDGES) return;
    int d = ei[N_EDGES + e];
    int pos = atomicAdd(&g_cur[d], 1);
    g_src[pos] = ei[e];
    g_dst[pos] = d;
    g_w[pos] = ew[e];
}

// ---------------------------------------------------------------------------
// Aggregation (R7 winner): warp owns 64 consecutive dst-sorted edges.
// Batches of 8: bulk index/weight loads, 8 independent float2 row gathers,
// register segmented sum, red.global flush only on dst change.
// ---------------------------------------------------------------------------
#define AGG_SPAN 64
#define N_SPANS (N_EDGES / AGG_SPAN)   // 12500

__device__ __forceinline__ void flush_v2(float* aggr, int dstn, int lane, float2 a) {
    float* p = aggr + (size_t)dstn * D + 2 * lane;
    u64 gp = (u64)__cvta_generic_to_global(p);
    asm volatile("red.global.add.v2.f32 [%0], {%1,%2};"
                 :: "l"(gp), "f"(a.x), "f"(a.y) : "memory");
}

__global__ void __launch_bounds__(256)
aggregate_kernel(const float* __restrict__ xin, float* __restrict__ aggr) {
    int warp = threadIdx.x >> 5, lane = threadIdx.x & 31;
    int span = blockIdx.x * 8 + warp;
    if (span >= N_SPANS) return;
    int e0 = span * AGG_SPAN;

    float2 acc = make_float2(0.f, 0.f);
    int cur = -1;

#pragma unroll 1
    for (int e = e0; e < e0 + AGG_SPAN; e += 8) {
        int4 i0 = *reinterpret_cast<const int4*>(g_src + e);
        int4 i1 = *reinterpret_cast<const int4*>(g_src + e + 4);
        int4 d0 = *reinterpret_cast<const int4*>(g_dst + e);
        int4 d1 = *reinterpret_cast<const int4*>(g_dst + e + 4);
        float4 w0 = *reinterpret_cast<const float4*>(g_w + e);
        float4 w1 = *reinterpret_cast<const float4*>(g_w + e + 4);
        int idx[8] = {i0.x, i0.y, i0.z, i0.w, i1.x, i1.y, i1.z, i1.w};
        int dst[8] = {d0.x, d0.y, d0.z, d0.w, d1.x, d1.y, d1.z, d1.w};
        float wt[8] = {w0.x, w0.y, w0.z, w0.w, w1.x, w1.y, w1.z, w1.w};

        float2 v[8];
#pragma unroll
        for (int j = 0; j < 8; ++j)
            v[j] = *reinterpret_cast<const float2*>(xin + (size_t)idx[j] * D + 2 * lane);

#pragma unroll
        for (int j = 0; j < 8; ++j) {
            if (dst[j] != cur) {
                if (cur >= 0) flush_v2(aggr, cur, lane, acc);
                acc = make_float2(0.f, 0.f);
                cur = dst[j];
            }
            acc.x += v[j].x * wt[j];
            acc.y += v[j].y * wt[j];
        }
    }
    if (cur >= 0) flush_v2(aggr, cur, lane, acc);
}

// ---------------------------------------------------------------------------
// Update: xout = l2norm( concat(l2norm(aggr), x) @ W + b ), FFMA2 GEMM.
// TB=32 rows -> smem 49KB -> 4 CTA/SM (32 warps). Persistent grid-stride.
// Thread map: tx (tid&15) -> 4 cols, ty (tid>>4, 16) -> 2 rows.
// Zeroes aggr rows after read.
// ---------------------------------------------------------------------------
#define TB 32
#define HSTR 132
#define N_TILES ((N_NODES + TB - 1) / TB)   // 1563
#define SMEM_BYTES ((128 * 64 + TB * HSTR) * 4)  // 49280 B

__device__ __forceinline__ u64 fma2(u64 a, u64 b, u64 c) {
    u64 d;
    asm("fma.rn.f32x2 %0, %1, %2, %3;" : "=l"(d) : "l"(a), "l"(b), "l"(c));
    return d;
}
__device__ __forceinline__ u64 bcast2(float x) {
    u64 d;
    asm("mov.b64 %0, {%1, %1};" : "=l"(d) : "f"(x));
    return d;
}
__device__ __forceinline__ u64 pack2(float lo, float hi) {
    u64 d;
    asm("mov.b64 %0, {%1, %2};" : "=l"(d) : "f"(lo), "f"(hi));
    return d;
}
__device__ __forceinline__ float2 unpack2(u64 v) {
    float lo, hi;
    asm("mov.b64 {%0, %1}, %2;" : "=f"(lo), "=f"(hi) : "l"(v));
    return make_float2(lo, hi);
}

__global__ void __launch_bounds__(256, 4)
update_kernel(float* __restrict__ aggr,
              const float* __restrict__ xin,
              const float* __restrict__ W,
              const float* __restrict__ b,
              float* __restrict__ xout) {
    extern __shared__ float smem[];
    float* W_s = smem;             // 128*64
    float* h_s = smem + 128 * 64;  // TB x HSTR

    int tid = threadIdx.x;
    int lane = tid & 31;
    int warp = tid >> 5;

    {
        const float4* Wv = reinterpret_cast<const float4*>(W);
        float4* Wsv = reinterpret_cast<float4*>(W_s);
#pragma unroll
        for (int i = 0; i < 8; ++i)
            Wsv[tid + i * 256] = Wv[tid + i * 256];
    }

    int tx = tid & 15, ty = tid >> 4;
    u64 bias0 = pack2(b[tx * 4 + 0], b[tx * 4 + 1]);
    u64 bias1 = pack2(b[tx * 4 + 2], b[tx * 4 + 3]);

    for (int tile = blockIdx.x; tile < N_TILES; tile += gridDim.x) {
        __syncthreads();

        // ---- Phase 1: warp handles 4 rows; load aggr+x, l2norm(aggr),
        //      fill h_s, zero aggr rows
#pragma unroll
        for (int j = 0; j < 4; ++j) {
            int r = warp * 4 + j;
            int node = tile * TB + r;
            float a0 = 0.f, a1 = 0.f, x0 = 0.f, x1 = 0.f;
            if (node < N_NODES) {
                const float* ar = aggr + (size_t)node * D;
                const float* xr = xin + (size_t)node * D;
                a0 = ar[lane]; a1 = ar[lane + 32];
                x0 = xr[lane]; x1 = xr[lane + 32];
                float* aw = aggr + (size_t)node * D;
                aw[lane] = 0.f; aw[lane + 32] = 0.f;
            }
            float ss = a0 * a0 + a1 * a1;
#pragma unroll
            for (int m = 16; m; m >>= 1) ss += __shfl_xor_sync(0xFFFFFFFFu, ss, m);
            float inv = 1.0f / fmaxf(sqrtf(ss), 1e-12f);
            float* hr = h_s + r * HSTR;
            hr[lane]      = a0 * inv;
            hr[lane + 32] = a1 * inv;
            hr[lane + 64] = x0;
            hr[lane + 96] = x1;
        }
        __syncthreads();

        // ---- Phase 2: GEMM 32x64 <- h[32][128] @ W[128][64], f32x2 FFMA
        u64 acc2[2][2];
#pragma unroll
        for (int i = 0; i < 2; ++i) { acc2[i][0] = bias0; acc2[i][1] = bias1; }

        const float* hbase = h_s + (ty * 2) * HSTR;
#pragma unroll 4
        for (int k = 0; k < 128; k += 4) {
            ulonglong2 wq0 = *reinterpret_cast<const ulonglong2*>(W_s + (k + 0) * 64 + tx * 4);
            ulonglong2 wq1 = *reinterpret_cast<const ulonglong2*>(W_s + (k + 1) * 64 + tx * 4);
            ulonglong2 wq2 = *reinterpret_cast<const ulonglong2*>(W_s + (k + 2) * 64 + tx * 4);
            ulonglong2 wq3 = *reinterpret_cast<const ulonglong2*>(W_s + (k + 3) * 64 + tx * 4);
#pragma unroll
            for (int i = 0; i < 2; ++i) {
                float4 h4 = *reinterpret_cast<const float4*>(hbase + i * HSTR + k);
                u64 hx = bcast2(h4.x);
                acc2[i][0] = fma2(hx, wq0.x, acc2[i][0]);
                acc2[i][1] = fma2(hx, wq0.y, acc2[i][1]);
                u64 hy = bcast2(h4.y);
                acc2[i][0] = fma2(hy, wq1.x, acc2[i][0]);
                acc2[i][1] = fma2(hy, wq1.y, acc2[i][1]);
                u64 hz = bcast2(h4.z);
                acc2[i][0] = fma2(hz, wq2.x, acc2[i][0]);
                acc2[i][1] = fma2(hz, wq2.y, acc2[i][1]);
                u64 hw = bcast2(h4.w);
                acc2[i][0] = fma2(hw, wq3.x, acc2[i][0]);
                acc2[i][1] = fma2(hw, wq3.y, acc2[i][1]);
            }
        }

        // ---- Phase 3: row l2norm across the 16 tx threads, store
#pragma unroll
        for (int i = 0; i < 2; ++i) {
            int r = ty * 2 + i;
            int node = tile * TB + r;
            float2 c0 = unpack2(acc2[i][0]);
            float2 c1 = unpack2(acc2[i][1]);
            float ss = c0.x * c0.x + c0.y * c0.y + c1.x * c1.x + c1.y * c1.y;
#pragma unroll
            for (int m = 8; m; m >>= 1) ss += __shfl_xor_sync(0xFFFFFFFFu, ss, m);
            float inv = 1.0f / fmaxf(sqrtf(ss), 1e-12f);
            if (node < N_NODES) {
                float4 o;
                o.x = c0.x * inv; o.y = c0.y * inv;
                o.z = c1.x * inv; o.w = c1.y * inv;
                *reinterpret_cast<float4*>(xout + (size_t)node * D + tx * 4) = o;
            }
        }
    }
}

// ---------------------------------------------------------------------------
extern "C" void kernel_launch(void* const* d_in, const int* in_sizes, int n_in,
                              void* d_out, int out_size) {
    const float* x  = (const float*)d_in[0];
    const int* ei   = (const int*)d_in[1];
    const float* ew = (const float*)d_in[2];
    const float* W  = (const float*)d_in[3];
    const float* b  = (const float*)d_in[4];
    float* out      = (float*)d_out;

    float *aggr, *buf0, *buf1;
    int* deg;
    cudaGetSymbolAddress((void**)&aggr, g_aggr);
    cudaGetSymbolAddress((void**)&buf0, g_buf0);
    cudaGetSymbolAddress((void**)&buf1, g_buf1);
    cudaGetSymbolAddress((void**)&deg, g_deg);

    cudaFuncSetAttribute(update_kernel,
                         cudaFuncAttributeMaxDynamicSharedMemorySize,
                         SMEM_BYTES);

    const int edge_blocks = (N_EDGES + 255) / 256;
    const int agg_blocks = (N_SPANS + 7) / 8;   // 1563
    const int upd_blocks = 148 * 4;             // persistent, 4 CTA/SM

    // CSR build (once per call)
    cudaMemsetAsync(deg, 0, N_NODES * sizeof(int), 0);
    hist_kernel<<<edge_blocks, 256>>>(ei);
    scan_kernel<<<1, SCAN_T>>>();
    permute_kernel<<<edge_blocks, 256>>>(ei, ew);

    // aggr starts zero; update re-zeros it each layer
    cudaMemsetAsync(aggr, 0, (size_t)N_NODES * D * sizeof(float), 0);

    const float* cur = x;
    for (int l = 0; l < N_LAYERS; ++l) {
        aggregate_kernel<<<agg_blocks, 256>>>(cur, aggr);
        float* nxt = (l == N_LAYERS - 1) ? out : ((l & 1) ? buf1 : buf0);
        update_kernel<<<upd_blocks, 256, SMEM_BYTES>>>(
            aggr, cur, W + (size_t)l * 2 * D * D, b + (size_t)l * D, nxt);
        cur = nxt;
    }
}

// round 10
// speedup vs baseline: 1.2300x; 1.2300x over previous
#include <cuda_runtime.h>
#include <stdint.h>

#define N_NODES 50000
#define N_EDGES 800000
#define D 64
#define N_LAYERS 12

typedef unsigned long long u64;

__device__ float g_aggr[N_NODES * D];
__device__ float g_buf0[N_NODES * D];
__device__ float g_buf1[N_NODES * D];
// CSR-sorted edge arrays (built once per launch)
__device__ int   g_deg[N_NODES];
__device__ int   g_cur[N_NODES];
__device__ int   g_sd[N_EDGES];    // packed: src | (dst << 16)
__device__ float g_w[N_EDGES];

// ---------------------------------------------------------------------------
// CSR build: histogram -> scan -> permute (sort edges by dst, pack src|dst)
// ---------------------------------------------------------------------------
__global__ void hist_kernel(const int* __restrict__ ei) {
    int e = blockIdx.x * blockDim.x + threadIdx.x;
    if (e < N_EDGES) atomicAdd(&g_deg[ei[N_EDGES + e]], 1);
}

#define SCAN_T 1024
#define SCAN_C 49
__global__ void scan_kernel() {
    __shared__ int part[SCAN_T];
    int t = threadIdx.x;
    int base = t * SCAN_C;
    int s = 0;
    for (int j = 0; j < SCAN_C; ++j) {
        int idx = base + j;
        if (idx < N_NODES) s += g_deg[idx];
    }
    part[t] = s;
    __syncthreads();
    for (int off = 1; off < SCAN_T; off <<= 1) {
        int v = (t >= off) ? part[t - off] : 0;
        __syncthreads();
        part[t] += v;
        __syncthreads();
    }
    int run = (t > 0) ? part[t - 1] : 0;
    for (int j = 0; j < SCAN_C; ++j) {
        int idx = base + j;
        if (idx < N_NODES) {
            g_cur[idx] = run;
            run += g_deg[idx];
        }
    }
}

__global__ void permute_kernel(const int* __restrict__ ei,
                               const float* __restrict__ ew) {
    int e = blockIdx.x * blockDim.x + threadIdx.x;
    if (e >= N_EDGES) return;
    int d = ei[N_EDGES + e];
    int pos = atomicAdd(&g_cur[d], 1);
    g_sd[pos] = ei[e] | (d << 16);   // src,dst both < 65536
    g_w[pos] = ew[e];
}

// ---------------------------------------------------------------------------
// Aggregation: warp owns 64 consecutive dst-sorted edges, 8 batches of 8.
// Two-stage pipeline: next batch's metadata prefetched before consuming
// current batch's gathers. Packed src|dst halves metadata loads.
// Register segmented sum, red.global flush only on dst change.
// ---------------------------------------------------------------------------
#define AGG_SPAN 64
#define N_SPANS (N_EDGES / AGG_SPAN)   // 12500

__device__ __forceinline__ void flush_v2(float* aggr, int dstn, int lane, float2 a) {
    float* p = aggr + (size_t)dstn * D + 2 * lane;
    u64 gp = (u64)__cvta_generic_to_global(p);
    asm volatile("red.global.add.v2.f32 [%0], {%1,%2};"
                 :: "l"(gp), "f"(a.x), "f"(a.y) : "memory");
}

__global__ void __launch_bounds__(256)
aggregate_kernel(const float* __restrict__ xin, float* __restrict__ aggr) {
    int warp = threadIdx.x >> 5, lane = threadIdx.x & 31;
    int span = blockIdx.x * 8 + warp;
    if (span >= N_SPANS) return;
    int e0 = span * AGG_SPAN;

    const int4* sdp = reinterpret_cast<const int4*>(g_sd + e0);
    const float4* wp = reinterpret_cast<const float4*>(g_w + e0);

    // Stage-in batch 0 metadata
    int4 sdA = sdp[0], sdB = sdp[1];
    float4 wA = wp[0], wB = wp[1];

    float2 acc = make_float2(0.f, 0.f);
    int cur = -1;

#pragma unroll
    for (int bt = 0; bt < 8; ++bt) {
        int sd[8] = {sdA.x, sdA.y, sdA.z, sdA.w, sdB.x, sdB.y, sdB.z, sdB.w};
        float wt[8] = {wA.x, wA.y, wA.z, wA.w, wB.x, wB.y, wB.z, wB.w};

        // Issue 8 independent gathers for the current batch
        float2 v[8];
#pragma unroll
        for (int j = 0; j < 8; ++j) {
            int src = sd[j] & 0xFFFF;
            v[j] = *reinterpret_cast<const float2*>(xin + (size_t)src * D + 2 * lane);
        }

        // Prefetch next batch metadata (overlaps with gather latency)
        if (bt < 7) {
            sdA = sdp[2 * bt + 2];
            sdB = sdp[2 * bt + 3];
            wA = wp[2 * bt + 2];
            wB = wp[2 * bt + 3];
        }

        // Consume: register segmented sum, flush on dst change
#pragma unroll
        for (int j = 0; j < 8; ++j) {
            int d = ((unsigned)sd[j]) >> 16;
            if (d != cur) {
                if (cur >= 0) flush_v2(aggr, cur, lane, acc);
                acc = make_float2(0.f, 0.f);
                cur = d;
            }
            acc.x += v[j].x * wt[j];
            acc.y += v[j].y * wt[j];
        }
    }
    if (cur >= 0) flush_v2(aggr, cur, lane, acc);
}

// ---------------------------------------------------------------------------
// Update (R8 winner): xout = l2norm( concat(l2norm(aggr), x) @ W + b )
// TB=64, FFMA2 GEMM, 391 blocks x exactly 2 tiles, 3 CTA/SM.
// Zeroes aggr rows after read (replaces per-layer memset).
// ---------------------------------------------------------------------------
#define TB 64
#define HSTR 132
#define N_TILES ((N_NODES + TB - 1) / TB)   // 782
#define SMEM_BYTES ((128 * 64 + TB * HSTR) * 4)

__device__ __forceinline__ u64 fma2(u64 a, u64 b, u64 c) {
    u64 d;
    asm("fma.rn.f32x2 %0, %1, %2, %3;" : "=l"(d) : "l"(a), "l"(b), "l"(c));
    return d;
}
__device__ __forceinline__ u64 bcast2(float x) {
    u64 d;
    asm("mov.b64 %0, {%1, %1};" : "=l"(d) : "f"(x));
    return d;
}
__device__ __forceinline__ u64 pack2(float lo, float hi) {
    u64 d;
    asm("mov.b64 %0, {%1, %2};" : "=l"(d) : "f"(lo), "f"(hi));
    return d;
}
__device__ __forceinline__ float2 unpack2(u64 v) {
    float lo, hi;
    asm("mov.b64 {%0, %1}, %2;" : "=f"(lo), "=f"(hi) : "l"(v));
    return make_float2(lo, hi);
}

__global__ void __launch_bounds__(256, 3)
update_kernel(float* __restrict__ aggr,
              const float* __restrict__ xin,
              const float* __restrict__ W,
              const float* __restrict__ b,
              float* __restrict__ xout) {
    extern __shared__ float smem[];
    float* W_s = smem;             // 128*64
    float* h_s = smem + 128 * 64;  // TB x HSTR

    int tid = threadIdx.x;
    int lane = tid & 31;
    int warp = tid >> 5;

    {
        const float4* Wv = reinterpret_cast<const float4*>(W);
        float4* Wsv = reinterpret_cast<float4*>(W_s);
#pragma unroll
        for (int i = 0; i < 8; ++i)
            Wsv[tid + i * 256] = Wv[tid + i * 256];
    }

    int tx = tid & 15, ty = tid >> 4;
    u64 bias0 = pack2(b[tx * 4 + 0], b[tx * 4 + 1]);
    u64 bias1 = pack2(b[tx * 4 + 2], b[tx * 4 + 3]);

    int p1_node = (warp << 3) + (lane >> 2);
    int p1_p = lane & 3;

    for (int tile = blockIdx.x; tile < N_TILES; tile += gridDim.x) {
        __syncthreads();

        // ---- Phase 1: load aggr + x, l2norm(aggr), fill h_s, zero aggr rows
        {
            int node = tile * TB + p1_node;
            float4 a[4], xv[4];
            if (node < N_NODES) {
                const float4* ar = reinterpret_cast<const float4*>(aggr + (size_t)node * D);
                const float4* xr = reinterpret_cast<const float4*>(xin + (size_t)node * D);
#pragma unroll
                for (int j = 0; j < 4; ++j) {
                    a[j]  = ar[p1_p + j * 4];
                    xv[j] = xr[p1_p + j * 4];
                }
                float4 z = make_float4(0.f, 0.f, 0.f, 0.f);
                float4* aw = reinterpret_cast<float4*>(aggr + (size_t)node * D);
#pragma unroll
                for (int j = 0; j < 4; ++j) aw[p1_p + j * 4] = z;
            } else {
#pragma unroll
                for (int j = 0; j < 4; ++j) {
                    a[j] = make_float4(0.f, 0.f, 0.f, 0.f);
                    xv[j] = a[j];
                }
            }
            float ss = 0.f;
#pragma unroll
            for (int j = 0; j < 4; ++j)
                ss += a[j].x * a[j].x + a[j].y * a[j].y
                    + a[j].z * a[j].z + a[j].w * a[j].w;
            ss += __shfl_xor_sync(0xFFFFFFFFu, ss, 1);
            ss += __shfl_xor_sync(0xFFFFFFFFu, ss, 2);
            float inv = 1.0f / fmaxf(sqrtf(ss), 1e-12f);

            float4* hr = reinterpret_cast<float4*>(h_s + p1_node * HSTR);
#pragma unroll
            for (int j = 0; j < 4; ++j) {
                float4 an;
                an.x = a[j].x * inv; an.y = a[j].y * inv;
                an.z = a[j].z * inv; an.w = a[j].w * inv;
                hr[p1_p + j * 4] = an;
                hr[16 + p1_p + j * 4] = xv[j];
            }
        }
        __syncthreads();

        // ---- Phase 2: GEMM with packed f32x2 FFMA
        u64 acc2[4][2];
#pragma unroll
        for (int i = 0; i < 4; ++i) { acc2[i][0] = bias0; acc2[i][1] = bias1; }

        const float* hbase = h_s + (ty * 4) * HSTR;
#pragma unroll 4
        for (int k = 0; k < 128; k += 4) {
            ulonglong2 wq0 = *reinterpret_cast<const ulonglong2*>(W_s + (k + 0) * 64 + tx * 4);
            ulonglong2 wq1 = *reinterpret_cast<const ulonglong2*>(W_s + (k + 1) * 64 + tx * 4);
            ulonglong2 wq2 = *reinterpret_cast<const ulonglong2*>(W_s + (k + 2) * 64 + tx * 4);
            ulonglong2 wq3 = *reinterpret_cast<const ulonglong2*>(W_s + (k + 3) * 64 + tx * 4);
#pragma unroll
            for (int i = 0; i < 4; ++i) {
                float4 h4 = *reinterpret_cast<const float4*>(hbase + i * HSTR + k);
                u64 hx = bcast2(h4.x);
                acc2[i][0] = fma2(hx, wq0.x, acc2[i][0]);
                acc2[i][1] = fma2(hx, wq0.y, acc2[i][1]);
                u64 hy = bcast2(h4.y);
                acc2[i][0] = fma2(hy, wq1.x, acc2[i][0]);
                acc2[i][1] = fma2(hy, wq1.y, acc2[i][1]);
                u64 hz = bcast2(h4.z);
                acc2[i][0] = fma2(hz, wq2.x, acc2[i][0]);
                acc2[i][1] = fma2(hz, wq2.y, acc2[i][1]);
                u64 hw = bcast2(h4.w);
                acc2[i][0] = fma2(hw, wq3.x, acc2[i][0]);
                acc2[i][1] = fma2(hw, wq3.y, acc2[i][1]);
            }
        }

        // ---- Phase 3: row l2norm across 16 tx threads, store
#pragma unroll
        for (int i = 0; i < 4; ++i) {
            int r = ty * 4 + i;
            int node = tile * TB + r;
            float2 c0 = unpack2(acc2[i][0]);
            float2 c1 = unpack2(acc2[i][1]);
            float ss = c0.x * c0.x + c0.y * c0.y + c1.x * c1.x + c1.y * c1.y;
#pragma unroll
            for (int m = 8; m; m >>= 1) ss += __shfl_xor_sync(0xFFFFFFFFu, ss, m);
            float inv = 1.0f / fmaxf(sqrtf(ss), 1e-12f);
            if (node < N_NODES) {
                float4 o;
                o.x = c0.x * inv; o.y = c0.y * inv;
                o.z = c1.x * inv; o.w = c1.y * inv;
                *reinterpret_cast<float4*>(xout + (size_t)node * D + tx * 4) = o;
            }
        }
    }
}

// ---------------------------------------------------------------------------
extern "C" void kernel_launch(void* const* d_in, const int* in_sizes, int n_in,
                              void* d_out, int out_size) {
    const float* x  = (const float*)d_in[0];
    const int* ei   = (const int*)d_in[1];
    const float* ew = (const float*)d_in[2];
    const float* W  = (const float*)d_in[3];
    const float* b  = (const float*)d_in[4];
    float* out      = (float*)d_out;

    float *aggr, *buf0, *buf1;
    int* deg;
    cudaGetSymbolAddress((void**)&aggr, g_aggr);
    cudaGetSymbolAddress((void**)&buf0, g_buf0);
    cudaGetSymbolAddress((void**)&buf1, g_buf1);
    cudaGetSymbolAddress((void**)&deg, g_deg);

    cudaFuncSetAttribute(update_kernel,
                         cudaFuncAttributeMaxDynamicSharedMemorySize,
                         SMEM_BYTES);

    const int edge_blocks = (N_EDGES + 255) / 256;
    const int agg_blocks = (N_SPANS + 7) / 8;   // 1563
    const int upd_blocks = 391;                 // 782 tiles / exactly 2 each

    // CSR build (once per call)
    cudaMemsetAsync(deg, 0, N_NODES * sizeof(int), 0);
    hist_kernel<<<edge_blocks, 256>>>(ei);
    scan_kernel<<<1, SCAN_T>>>();
    permute_kernel<<<edge_blocks, 256>>>(ei, ew);

    // aggr starts zero; update re-zeros it each layer
    cudaMemsetAsync(aggr, 0, (size_t)N_NODES * D * sizeof(float), 0);

    const float* cur = x;
    for (int l = 0; l < N_LAYERS; ++l) {
        aggregate_kernel<<<agg_blocks, 256>>>(cur, aggr);
        float* nxt = (l == N_LAYERS - 1) ? out : ((l & 1) ? buf1 : buf0);
        update_kernel<<<upd_blocks, 256, SMEM_BYTES>>>(
            aggr, cur, W + (size_t)l * 2 * D * D, b + (size_t)l * D, nxt);
        cur = nxt;
    }
}